// round 8
// baseline (speedup 1.0000x reference)
#include <cuda_runtime.h>
#include <cuda_fp16.h>
#include <math.h>
#include <stdint.h>

// ---------------------------------------------------------------------------
// B=16, C=3, H=W=512, P=16 -> 16384 tokens; D=768, F=3072, NH=12, dh=64
// ---------------------------------------------------------------------------
#define MTOK   16384
#define DMODEL 768
#define FFDIM  3072
#define QKVDIM 2304

// ------------------------- scratch (device globals) ------------------------
__device__ float  g_x[MTOK * DMODEL];       // identity #1 (fp32)
__device__ float  g_y[MTOK * DMODEL];       // patch-embed out (fp32)
__device__ float  g_z[MTOK * DMODEL];       // identity #2 (fp32)
__device__ __half g_qkv16[MTOK * QKVDIM];   // qkv (fp16)
__device__ __half g_h16[MTOK * FFDIM];      // im2col, then FF hidden (fp16)
__device__ __half g_actA[MTOK * DMODEL];    // fp16 activation ping
__device__ __half g_actB[MTOK * DMODEL];    // fp16 activation pong
__device__ __half g_w1h[FFDIM * DMODEL];    // ff1_w^T  [N,K] fp16
__device__ __half g_w2h[DMODEL * FFDIM];    // ff2_w^T
__device__ __half g_wqh[QKVDIM * DMODEL];   // qkv_w^T
__device__ __half g_wph[DMODEL * DMODEL];   // proj_w^T
__device__ __half g_pwh[DMODEL * DMODEL];   // patch_w (already [N,K]) fp16
__device__ float  g_invfreq[DMODEL / 2];

// ------------------------------ PTX helpers ---------------------------------
__device__ __forceinline__ uint32_t smem_to_u32(const void* p) {
    uint32_t a;
    asm("{ .reg .u64 t; cvta.to.shared.u64 t, %1; cvt.u32.u64 %0, t; }"
        : "=r"(a) : "l"(p));
    return a;
}
#define CP_ASYNC16(dst, src) \
    asm volatile("cp.async.cg.shared.global [%0], [%1], 16;" \
        :: "r"(dst), "l"(src))
#define CP_COMMIT() asm volatile("cp.async.commit_group;" ::: "memory")
#define CP_WAIT1()  asm volatile("cp.async.wait_group 1;" ::: "memory")

#define LDMATRIX_X4(r0, r1, r2, r3, addr) \
    asm volatile("ldmatrix.sync.aligned.m8n8.x4.shared.b16 {%0,%1,%2,%3}, [%4];" \
        : "=r"(r0), "=r"(r1), "=r"(r2), "=r"(r3) : "r"(addr))

#define MMA_F16(c, a, b) \
    asm volatile("mma.sync.aligned.m16n8k16.row.col.f32.f16.f16.f32 " \
        "{%0,%1,%2,%3}, {%4,%5,%6,%7}, {%8,%9}, {%0,%1,%2,%3};" \
        : "+f"((c)[0]), "+f"((c)[1]), "+f"((c)[2]), "+f"((c)[3]) \
        : "r"((a)[0]), "r"((a)[1]), "r"((a)[2]), "r"((a)[3]), \
          "r"((b)[0]), "r"((b)[1]))

// ------------------------------- small kernels ------------------------------
__device__ __forceinline__ float gelu_tanh(float x) {
    float x3 = x * x * x;
    return 0.5f * x * (1.f + tanhf(0.7978845608028654f * (x + 0.044715f * x3)));
}

__global__ void build_invfreq_kernel(float* inv) {
    int i = blockIdx.x * blockDim.x + threadIdx.x;
    if (i < DMODEL / 2)
        inv[i] = (float)exp(-(double)i * (2.0 / (double)DMODEL) * log(10000.0));
}

// out[c*R + r] = (half)in[r*C + c]
__global__ void transpose_h_kernel(const float* __restrict__ in,
                                   __half* __restrict__ out, int R, int C) {
    __shared__ float t[32][33];
    int bx = blockIdx.x * 32, by = blockIdx.y * 32;
    int x = bx + threadIdx.x;
    #pragma unroll
    for (int j = 0; j < 32; j += 8)
        t[threadIdx.y + j][threadIdx.x] = in[(size_t)(by + threadIdx.y + j) * C + x];
    __syncthreads();
    int xo = by + threadIdx.x;
    #pragma unroll
    for (int j = 0; j < 32; j += 8)
        out[(size_t)(bx + threadIdx.y + j) * R + xo] =
            __float2half(t[threadIdx.x][threadIdx.y + j]);
}

__global__ void f2h_kernel(const float* __restrict__ in, __half* __restrict__ out,
                           int n) {
    int i = blockIdx.x * blockDim.x + threadIdx.x;
    if (i * 2 < n) {
        float2 v = *reinterpret_cast<const float2*>(&in[i * 2]);
        *reinterpret_cast<__half2*>(&out[i * 2]) = __floats2half2_rn(v.x, v.y);
    }
}

__global__ void im2col_h_kernel(const float* __restrict__ in,
                                __half* __restrict__ A) {
    int idx = blockIdx.x * blockDim.x + threadIdx.x;
    int m = idx / 192;
    int k = (idx % 192) * 4;
    int b = m >> 10, n = m & 1023;
    int hp = n >> 5, wp = n & 31;
    int c = k >> 8, rem = k & 255;
    int p = rem >> 4, q = rem & 15;
    const float* src = in + ((((size_t)b * 3 + c) * 512) + (size_t)hp * 16 + p) * 512
                          + (size_t)wp * 16 + q;
    float4 v = *reinterpret_cast<const float4*>(src);
    __half2* dst = reinterpret_cast<__half2*>(&A[(size_t)m * DMODEL + k]);
    dst[0] = __floats2half2_rn(v.x, v.y);
    dst[1] = __floats2half2_rn(v.z, v.w);
}

__global__ void ln_pe_kernel(const float* __restrict__ x, const float* __restrict__ gam,
                             const float* __restrict__ bet, const float* __restrict__ invfreq,
                             float* __restrict__ out, __half* __restrict__ outh) {
    __shared__ float ss[8], sq[8];
    int m = blockIdx.x;
    int t = threadIdx.x;
    const float* row = x + (size_t)m * DMODEL;
    float v0 = row[t], v1 = row[t + 256], v2 = row[t + 512];
    float s = v0 + v1 + v2;
    float q = v0 * v0 + v1 * v1 + v2 * v2;
    #pragma unroll
    for (int o = 16; o > 0; o >>= 1) {
        s += __shfl_down_sync(0xFFFFFFFFu, s, o);
        q += __shfl_down_sync(0xFFFFFFFFu, q, o);
    }
    int warp = t >> 5, lane = t & 31;
    if (lane == 0) { ss[warp] = s; sq[warp] = q; }
    __syncthreads();
    if (t == 0) {
        float S = 0.f, Q = 0.f;
        #pragma unroll
        for (int i = 0; i < 8; i++) { S += ss[i]; Q += sq[i]; }
        float mean = S * (1.f / 768.f);
        float var = Q * (1.f / 768.f) - mean * mean;
        ss[0] = mean;
        sq[0] = rsqrtf(var + 1e-5f);
    }
    __syncthreads();
    float mean = ss[0], rstd = sq[0];
    int n = m & 1023;
    float vals[3] = {v0, v1, v2};
    #pragma unroll
    for (int e = 0; e < 3; e++) {
        int d = t + e * 256;
        float ang = (float)n * invfreq[d >> 1];
        float pe = (d & 1) ? cosf(ang) : sinf(ang);
        float r = (vals[e] - mean) * rstd * gam[d] + bet[d] + pe;
        out[(size_t)m * DMODEL + d] = r;
        outh[(size_t)m * DMODEL + d] = __float2half(r);
    }
}

// ---------------------- fp16 mma.sync GEMM (256x128x64, 3-stage) ------------
// C = A[M,K] @ Bw^T (+bias, opt GELU, opt +res). Bw is [N,K] fp16, K contig.
// 256 threads = 8 warps (4 x 2), warp tile 64x64; per k16: 8 ldmatrix, 32 MMA.
// 3-stage cp.async pipeline, one __syncthreads per K-step.
// Requires M%256==0, N%128==0, K%64==0.
#define STAGE_BYTES 49152            // A 32KB + B 16KB per stage
#define GEMM_SMEM_BYTES (3 * STAGE_BYTES)   // 147456

template <bool GELU, bool RES>
__global__ __launch_bounds__(256, 1)
void gemm_h(const __half* __restrict__ A, const __half* __restrict__ Bw,
            const float* __restrict__ bias, const float* __restrict__ res,
            float* __restrict__ C32, __half* __restrict__ C16,
            int M, int N, int K) {
    extern __shared__ char smraw[];
    const uint32_t sb = smem_to_u32(smraw);

    const int tid = threadIdx.x;
    const int m0 = blockIdx.y * 256;
    const int n0 = blockIdx.x * 128;
    const int lane = tid & 31, wid = tid >> 5;
    const int warpM = wid >> 1, warpN = wid & 1;   // 4 x 2
    const int g = lane >> 2, q = lane & 3;
    const int sel = lane >> 3, rr = lane & 7;

    float acc[4][8][4];
    #pragma unroll
    for (int i = 0; i < 4; i++)
        #pragma unroll
        for (int j = 0; j < 8; j++)
            #pragma unroll
            for (int k = 0; k < 4; k++) acc[i][j][k] = 0.f;

    // cp.async mapping: A 2048 chunks (8/thread), B 1024 chunks (4/thread)
    auto load_tile = [&](int stg, int k0) {
        const uint32_t aB = sb + (uint32_t)stg * STAGE_BYTES;
        const uint32_t bB = aB + 32768;
        #pragma unroll
        for (int i = 0; i < 8; i++) {
            int idx = tid + i * 256;
            int r = idx >> 3, c = idx & 7;
            uint32_t sw = (uint32_t)(r * 128 + ((c ^ (r & 7)) << 4));
            CP_ASYNC16(aB + sw, A + (size_t)(m0 + r) * K + k0 + c * 8);
        }
        #pragma unroll
        for (int i = 0; i < 4; i++) {
            int idx = tid + i * 256;
            int r = idx >> 3, c = idx & 7;
            uint32_t sw = (uint32_t)(r * 128 + ((c ^ (r & 7)) << 4));
            CP_ASYNC16(bB + sw, Bw + (size_t)(n0 + r) * K + k0 + c * 8);
        }
    };

    // ldmatrix row geometry
    int mrow[4], nrow[4];
    #pragma unroll
    for (int mt = 0; mt < 4; mt++)
        mrow[mt] = warpM * 64 + mt * 16 + ((sel & 1) << 3) + rr;
    #pragma unroll
    for (int np = 0; np < 4; np++)
        nrow[np] = warpN * 64 + np * 16 + ((sel >> 1) << 3) + rr;
    const int achk = sel >> 1;
    const int bchk = sel & 1;

    const int nsteps = K >> 6;
    load_tile(0, 0);
    CP_COMMIT();
    load_tile(1, 64);
    CP_COMMIT();

    for (int s = 0; s < nsteps; s++) {
        CP_WAIT1();
        __syncthreads();
        if (s + 2 < nsteps) load_tile((s + 2) % 3, (s + 2) * 64);
        CP_COMMIT();

        const uint32_t aB = sb + (uint32_t)(s % 3) * STAGE_BYTES;
        const uint32_t bB = aB + 32768;
        #pragma unroll
        for (int step = 0; step < 4; step++) {
            const int c0 = step * 2;
            uint32_t af[4][4], bf[8][2];
            #pragma unroll
            for (int mt = 0; mt < 4; mt++) {
                int r = mrow[mt];
                uint32_t addr = aB + r * 128 + (((c0 + achk) ^ (r & 7)) << 4);
                LDMATRIX_X4(af[mt][0], af[mt][1], af[mt][2], af[mt][3], addr);
            }
            #pragma unroll
            for (int np = 0; np < 4; np++) {
                int r = nrow[np];
                uint32_t addr = bB + r * 128 + (((c0 + bchk) ^ (r & 7)) << 4);
                LDMATRIX_X4(bf[2 * np][0], bf[2 * np][1],
                            bf[2 * np + 1][0], bf[2 * np + 1][1], addr);
            }
            #pragma unroll
            for (int mt = 0; mt < 4; mt++)
                #pragma unroll
                for (int nt = 0; nt < 8; nt++)
                    MMA_F16(acc[mt][nt], af[mt], bf[nt]);
        }
    }

    // epilogue
    #pragma unroll
    for (int mt = 0; mt < 4; mt++) {
        #pragma unroll
        for (int half = 0; half < 2; half++) {
            const int row = m0 + warpM * 64 + mt * 16 + g + half * 8;
            float* c32row = C32 ? (C32 + (size_t)row * N) : nullptr;
            __half* c16row = C16 ? (C16 + (size_t)row * N) : nullptr;
            const float* rrow = RES ? (res + (size_t)row * N) : nullptr;
            #pragma unroll
            for (int nt = 0; nt < 8; nt++) {
                const int col = n0 + warpN * 64 + nt * 8 + 2 * q;
                float v0 = acc[mt][nt][half * 2 + 0] + bias[col];
                float v1 = acc[mt][nt][half * 2 + 1] + bias[col + 1];
                if (GELU) { v0 = gelu_tanh(v0); v1 = gelu_tanh(v1); }
                if (RES)  { v0 += rrow[col]; v1 += rrow[col + 1]; }
                if (c32row)
                    *reinterpret_cast<float2*>(&c32row[col]) = make_float2(v0, v1);
                if (c16row)
                    *reinterpret_cast<__half2*>(&c16row[col]) = __floats2half2_rn(v0, v1);
            }
        }
    }
}

// --------------------------- window attention --------------------------------
// fp16 qkv input, fp32 math in smem (unchanged numerics), fp16 output.
__global__ __launch_bounds__(256)
void attn_kernel(const __half* __restrict__ qkv, __half* __restrict__ o) {
    __shared__ float sA[64 * 64];
    __shared__ float sK[64 * 64];
    __shared__ float sS[64 * 64];

    int wh = blockIdx.x;
    int h = wh % 12;
    int w = wh / 12;
    int m0 = (w >> 4) * 1024 + (w & 15) * 64;

    int tid = threadIdx.x;
    int lane = tid & 31;
    const __half* base = qkv + (size_t)m0 * QKVDIM;
    int qoff = h * 64, koff = 768 + h * 64, voff = 1536 + h * 64;

    for (int u = tid; u < 1024; u += 256) {
        int r = u >> 4;
        int c4 = (u & 15) << 2;
        const __half2* sq = reinterpret_cast<const __half2*>(
            &base[(size_t)r * QKVDIM + qoff + c4]);
        const __half2* sk = reinterpret_cast<const __half2*>(
            &base[(size_t)r * QKVDIM + koff + c4]);
        float2 q0 = __half22float2(sq[0]), q1 = __half22float2(sq[1]);
        float2 k0 = __half22float2(sk[0]), k1 = __half22float2(sk[1]);
        *reinterpret_cast<float4*>(&sA[r * 64 + c4]) = make_float4(q0.x, q0.y, q1.x, q1.y);
        *reinterpret_cast<float4*>(&sK[r * 64 + c4]) = make_float4(k0.x, k0.y, k1.x, k1.y);
    }
    __syncthreads();

    int i0 = (tid >> 4) << 2;
    int j0 = (tid & 15) << 2;
    {
        float accS[4][4] = {};
        for (int kk = 0; kk < 64; kk++) {
            int ke = (kk + lane) & 63;
            float a[4], b[4];
            #pragma unroll
            for (int ii = 0; ii < 4; ii++) a[ii] = sA[(i0 + ii) * 64 + ke];
            #pragma unroll
            for (int jj = 0; jj < 4; jj++) b[jj] = sK[(j0 + jj) * 64 + ke];
            #pragma unroll
            for (int ii = 0; ii < 4; ii++)
                #pragma unroll
                for (int jj = 0; jj < 4; jj++)
                    accS[ii][jj] += a[ii] * b[jj];
        }
        #pragma unroll
        for (int ii = 0; ii < 4; ii++)
            #pragma unroll
            for (int jj = 0; jj < 4; jj++)
                sS[(i0 + ii) * 64 + (j0 + jj)] = accS[ii][jj] * 0.125f;
    }
    __syncthreads();

    if (tid < 64) {
        int i = tid;
        float mx = -1e30f;
        for (int j = 0; j < 64; j++)
            mx = fmaxf(mx, sS[i * 64 + ((j + tid) & 63)]);
        float sum = 0.f;
        for (int j = 0; j < 64; j++) {
            int jj = (j + tid) & 63;
            float e = expf(sS[i * 64 + jj] - mx);
            sS[i * 64 + jj] = e;
            sum += e;
        }
        float invs = 1.f / sum;
        for (int j = 0; j < 64; j++) {
            int jj = (j + tid) & 63;
            sS[i * 64 + jj] *= invs;
        }
    }
    for (int u = tid; u < 1024; u += 256) {
        int r = u >> 4;
        int c4 = (u & 15) << 2;
        const __half2* sv = reinterpret_cast<const __half2*>(
            &base[(size_t)r * QKVDIM + voff + c4]);
        float2 v0 = __half22float2(sv[0]), v1 = __half22float2(sv[1]);
        *reinterpret_cast<float4*>(&sA[r * 64 + c4]) = make_float4(v0.x, v0.y, v1.x, v1.y);
    }
    __syncthreads();

    int d0 = j0;
    float accO[4][4] = {};
    for (int j = 0; j < 64; j++) {
        int je = (j + lane) & 63;
        float s[4], vv[4];
        #pragma unroll
        for (int ii = 0; ii < 4; ii++) s[ii] = sS[(i0 + ii) * 64 + je];
        #pragma unroll
        for (int dd = 0; dd < 4; dd++) vv[dd] = sA[je * 64 + d0 + dd];
        #pragma unroll
        for (int ii = 0; ii < 4; ii++)
            #pragma unroll
            for (int dd = 0; dd < 4; dd++)
                accO[ii][dd] += s[ii] * vv[dd];
    }
    #pragma unroll
    for (int ii = 0; ii < 4; ii++) {
        __half* orow = o + (size_t)(m0 + i0 + ii) * DMODEL + h * 64 + d0;
        *reinterpret_cast<__half2*>(orow) = __floats2half2_rn(accO[ii][0], accO[ii][1]);
        *reinterpret_cast<__half2*>(orow + 2) = __floats2half2_rn(accO[ii][2], accO[ii][3]);
    }
}

// ------------------------------- launcher -----------------------------------
extern "C" void kernel_launch(void* const* d_in, const int* in_sizes, int n_in,
                              void* d_out, int out_size) {
    (void)in_sizes; (void)n_in; (void)out_size;
    const float* input   = (const float*)d_in[0];
    const float* patch_w = (const float*)d_in[1];
    const float* patch_b = (const float*)d_in[2];
    const float* ln_g    = (const float*)d_in[3];
    const float* ln_b    = (const float*)d_in[4];
    const float* qkv_w   = (const float*)d_in[5];
    const float* qkv_b   = (const float*)d_in[6];
    const float* proj_w  = (const float*)d_in[7];
    const float* proj_b  = (const float*)d_in[8];
    const float* ff1_w   = (const float*)d_in[9];
    const float* ff1_b   = (const float*)d_in[10];
    const float* ff2_w   = (const float*)d_in[11];
    const float* ff2_b   = (const float*)d_in[12];
    float* out = (float*)d_out;

    float *x, *y, *z, *invf;
    __half *qkv16, *h16, *actA, *actB, *w1h, *w2h, *wqh, *wph, *pwh;
    cudaGetSymbolAddress((void**)&x,     g_x);
    cudaGetSymbolAddress((void**)&y,     g_y);
    cudaGetSymbolAddress((void**)&z,     g_z);
    cudaGetSymbolAddress((void**)&qkv16, g_qkv16);
    cudaGetSymbolAddress((void**)&h16,   g_h16);
    cudaGetSymbolAddress((void**)&actA,  g_actA);
    cudaGetSymbolAddress((void**)&actB,  g_actB);
    cudaGetSymbolAddress((void**)&w1h,   g_w1h);
    cudaGetSymbolAddress((void**)&w2h,   g_w2h);
    cudaGetSymbolAddress((void**)&wqh,   g_wqh);
    cudaGetSymbolAddress((void**)&wph,   g_wph);
    cudaGetSymbolAddress((void**)&pwh,   g_pwh);
    cudaGetSymbolAddress((void**)&invf,  g_invfreq);

    cudaFuncSetAttribute((const void*)gemm_h<false, false>,
                         cudaFuncAttributeMaxDynamicSharedMemorySize, GEMM_SMEM_BYTES);
    cudaFuncSetAttribute((const void*)gemm_h<true, false>,
                         cudaFuncAttributeMaxDynamicSharedMemorySize, GEMM_SMEM_BYTES);
    cudaFuncSetAttribute((const void*)gemm_h<false, true>,
                         cudaFuncAttributeMaxDynamicSharedMemorySize, GEMM_SMEM_BYTES);

    // prep
    build_invfreq_kernel<<<2, 192>>>(invf);
    transpose_h_kernel<<<dim3(96, 24), dim3(32, 8)>>>(ff1_w, w1h, DMODEL, FFDIM);
    transpose_h_kernel<<<dim3(24, 96), dim3(32, 8)>>>(ff2_w, w2h, FFDIM, DMODEL);
    transpose_h_kernel<<<dim3(72, 24), dim3(32, 8)>>>(qkv_w, wqh, DMODEL, QKVDIM);
    transpose_h_kernel<<<dim3(24, 24), dim3(32, 8)>>>(proj_w, wph, DMODEL, DMODEL);
    f2h_kernel<<<(DMODEL * DMODEL / 2 + 255) / 256, 256>>>(patch_w, pwh,
                                                           DMODEL * DMODEL);
    im2col_h_kernel<<<(MTOK * DMODEL / 4) / 256, 256>>>(input, h16);

    // patch embed -> y (fp32)
    gemm_h<false, false><<<dim3(6, 64), 256, GEMM_SMEM_BYTES>>>(
        h16, pwh, patch_b, nullptr, y, nullptr, MTOK, DMODEL, DMODEL);
    // LN + PE -> x (fp32 identity) + actA (fp16)
    ln_pe_kernel<<<MTOK, 256>>>(y, ln_g, ln_b, invf, x, actA);

    // ff block 1
    gemm_h<true, false><<<dim3(24, 64), 256, GEMM_SMEM_BYTES>>>(
        actA, w1h, ff1_b, nullptr, nullptr, h16, MTOK, FFDIM, DMODEL);
    gemm_h<false, false><<<dim3(6, 64), 256, GEMM_SMEM_BYTES>>>(
        h16, w2h, ff2_b, nullptr, nullptr, actB, MTOK, DMODEL, FFDIM);

    // attention
    gemm_h<false, false><<<dim3(18, 64), 256, GEMM_SMEM_BYTES>>>(
        actB, wqh, qkv_b, nullptr, nullptr, qkv16, MTOK, QKVDIM, DMODEL);
    attn_kernel<<<3072, 256>>>(qkv16, actA);
    gemm_h<false, true><<<dim3(6, 64), 256, GEMM_SMEM_BYTES>>>(
        actA, wph, proj_b, x, z, actB, MTOK, DMODEL, DMODEL);

    // ff block 2 (residual into d_out)
    gemm_h<true, false><<<dim3(24, 64), 256, GEMM_SMEM_BYTES>>>(
        actB, w1h, ff1_b, nullptr, nullptr, h16, MTOK, FFDIM, DMODEL);
    gemm_h<false, true><<<dim3(6, 64), 256, GEMM_SMEM_BYTES>>>(
        h16, w2h, ff2_b, z, out, nullptr, MTOK, DMODEL, FFDIM);
}